// round 3
// baseline (speedup 1.0000x reference)
#include <cuda_runtime.h>
#include <math.h>
#include <stdint.h>

// ---------------------------------------------------------------------------
// Problem constants
// ---------------------------------------------------------------------------
#define CF      128       // feature / guide channels
#define CELLS   4096      // 64*64 low-res cells
#define NPIX    65536     // 256*256 hi-res pixels per batch
#define PTOT    131072    // B * NPIX total pixels
#define CH      32768     // pixels per chunk
#define NCHUNK  (PTOT / CH)
#define RCH     (CH * 4)  // MLP rows per chunk = 131072

// ---------------------------------------------------------------------------
// Static device scratch (~1.22 GB total; must stay < ~2 GB for aarch64 .bss
// relocation reach). All per-pixel buffers are chunked.
// ---------------------------------------------------------------------------
__device__ __align__(16) float g_Xf [2 * CELLS * CF];            //   4 MB
__device__ __align__(16) float g_Xlr[2 * CELLS * CF];            //   4 MB
__device__ __align__(16) float g_Xhr[(size_t)PTOT * CF];         //  64 MB
__device__ __align__(16) float g_W1g[CF * 1024];                 // 0.5 MB
__device__ __align__(16) float g_A  [(size_t)2 * CELLS * 1024];  //  32 MB
__device__ __align__(16) float g_Bt [(size_t)2 * CELLS * 1024];  //  32 MB
__device__ __align__(16) float g_G  [(size_t)CH * 1024];         // 128 MB
__device__ __align__(16) float g_h1 [(size_t)RCH * 1024];        // 512 MB
__device__ __align__(16) float g_h2 [(size_t)RCH * 512];         // 256 MB
__device__ __align__(16) float g_h3 [(size_t)RCH * 256];         // 128 MB
__device__ __align__(16) float g_h4 [(size_t)RCH * 128];         //  64 MB

// ---------------------------------------------------------------------------
// Pack: [B*C, S] channel-major -> [B*S, C] row-major (tiled transpose)
// ---------------------------------------------------------------------------
__global__ void k_transpose(const float* __restrict__ in, float* __restrict__ out,
                            int C, int S) {
    __shared__ float tile[32][33];
    const int b  = blockIdx.z;
    const int s0 = blockIdx.x * 32;
    const int c0 = blockIdx.y * 32;
    const int tx = threadIdx.x, ty = threadIdx.y;   // blockDim = (32, 8)
#pragma unroll
    for (int i = 0; i < 32; i += 8)
        tile[ty + i][tx] = in[(size_t)(b * C + c0 + ty + i) * S + (s0 + tx)];
    __syncthreads();
#pragma unroll
    for (int i = 0; i < 32; i += 8)
        out[(size_t)(b * S + s0 + ty + i) * C + (c0 + tx)] = tile[tx][ty + i];
}

// g_W1g[c][j] = w1[128+c][j] + w1[256+c][j]
__global__ void k_w1g(const float* __restrict__ w1) {
    int idx = blockIdx.x * 256 + threadIdx.x;   // < 128*1024
    g_W1g[idx] = w1[(size_t)128 * 1024 + idx] + w1[(size_t)256 * 1024 + idx];
}

// ---------------------------------------------------------------------------
// SGEMM: C[M,N] = act(A[M,K] @ W[K,N] + bias), row-major, 128x128x16 tiles,
// 8x8 per-thread register blocking, 256 threads. All dims divisible.
// ---------------------------------------------------------------------------
template<bool RELU>
__global__ __launch_bounds__(256)
void k_sgemm(const float* __restrict__ A, const float* __restrict__ W,
             const float* __restrict__ bias, float* __restrict__ C,
             int M, int N, int K) {
    __shared__ float As[16][128];
    __shared__ float Ws[16][128];
    const int tid = threadIdx.x;
    const int m0  = blockIdx.y * 128;
    const int n0  = blockIdx.x * 128;
    const int ty  = tid >> 4;         // 0..15 (M direction)
    const int tx  = tid & 15;         // 0..15 (N direction)

    float acc[8][8];
#pragma unroll
    for (int i = 0; i < 8; i++)
#pragma unroll
        for (int j = 0; j < 8; j++) acc[i][j] = 0.f;

    for (int k0 = 0; k0 < K; k0 += 16) {
#pragma unroll
        for (int t = 0; t < 2; t++) {
            int idx = tid + t * 256;
            // A tile: 128 rows x 16 cols, store transposed
            int ar = idx >> 2;
            int ac = (idx & 3) << 2;
            float4 v = *(const float4*)(A + (size_t)(m0 + ar) * K + (k0 + ac));
            As[ac + 0][ar] = v.x;
            As[ac + 1][ar] = v.y;
            As[ac + 2][ar] = v.z;
            As[ac + 3][ar] = v.w;
            // W tile: 16 rows x 128 cols, direct
            int wr = idx >> 5;
            int wc = (idx & 31) << 2;
            *(float4*)&Ws[wr][wc] =
                *(const float4*)(W + (size_t)(k0 + wr) * N + (n0 + wc));
        }
        __syncthreads();
#pragma unroll
        for (int k = 0; k < 16; k++) {
            float a[8], w[8];
            *(float4*)&a[0] = *(const float4*)&As[k][ty * 8];
            *(float4*)&a[4] = *(const float4*)&As[k][ty * 8 + 4];
            *(float4*)&w[0] = *(const float4*)&Ws[k][tx * 8];
            *(float4*)&w[4] = *(const float4*)&Ws[k][tx * 8 + 4];
#pragma unroll
            for (int i = 0; i < 8; i++)
#pragma unroll
                for (int j = 0; j < 8; j++)
                    acc[i][j] += a[i] * w[j];
        }
        __syncthreads();
    }

    float bv[8];
#pragma unroll
    for (int j = 0; j < 8; j++) bv[j] = bias ? bias[n0 + tx * 8 + j] : 0.f;

#pragma unroll
    for (int i = 0; i < 8; i++) {
        size_t row = (size_t)(m0 + ty * 8 + i);
        float o[8];
#pragma unroll
        for (int j = 0; j < 8; j++) {
            float v = acc[i][j] + bv[j];
            o[j] = RELU ? fmaxf(v, 0.f) : v;
        }
        *(float4*)(C + row * N + n0 + tx * 8)     = *(float4*)&o[0];
        *(float4*)(C + row * N + n0 + tx * 8 + 4) = *(float4*)&o[4];
    }
}

// ---------------------------------------------------------------------------
// Layer-1 assembly for one chunk: per pixel (p0 + blockIdx.x) and offset k,
// gather precomputed partial products, add rank-2 rel_coord term + bias,
// ReLU -> g_h1 local row. Replicates nearest_sample rounding & zero-fill.
// ---------------------------------------------------------------------------
__global__ __launch_bounds__(256)
void k_assemble(const float* __restrict__ coord,
                const float* __restrict__ w1,
                const float* __restrict__ b1, int p0) {
    const int pl = blockIdx.x;          // local pixel id within chunk
    const int p  = p0 + pl;             // global pixel id (b*65536 + pix)
    const int b  = p >> 16;
    const int jc = threadIdx.x << 2;    // 4 cols per thread, 256 threads -> 1024

    const float y = coord[(size_t)p * 2 + 0];
    const float x = coord[(size_t)p * 2 + 1];

    float4 Gv = *(const float4*)(g_G + (size_t)pl * 1024 + jc);
    float4 wy = *(const float4*)(w1 + (size_t)384 * 1024 + jc);
    float4 wx = *(const float4*)(w1 + (size_t)385 * 1024 + jc);
    float4 bv = *(const float4*)(b1 + jc);

#pragma unroll
    for (int k = 0; k < 4; k++) {
        const float vx = (k >= 2) ? 1.f : -1.f;     // loop order: vx outer
        const float vy = (k & 1)  ? 1.f : -1.f;     // vy inner
        const float cy = y + vx * (1.f / 64.f);
        const float cx = x + vy * (1.f / 64.f);
        const float fy = (cy + 1.f) * 32.f - 0.5f;
        const float fx = (cx + 1.f) * 32.f - 0.5f;
        const int iy = (int)floorf(fy + 0.5f);
        const int ix = (int)floorf(fx + 0.5f);
        const bool valid = (iy >= 0) && (iy < 64) && (ix >= 0) && (ix < 64);
        const int iyc = min(max(iy, 0), 63);
        const int ixc = min(max(ix, 0), 63);
        // q_coord is zeroed when invalid (reference semantics)
        const float qy = valid ? (-1.f + (1.f / 64.f) + (2.f / 64.f) * (float)iyc) : 0.f;
        const float qx = valid ? (-1.f + (1.f / 64.f) + (2.f / 64.f) * (float)ixc) : 0.f;
        const float ry = (y - qy) * 64.f;
        const float rx = (x - qx) * 64.f;

        float4 acc;
        acc.x = Gv.x + bv.x + ry * wy.x + rx * wx.x;
        acc.y = Gv.y + bv.y + ry * wy.y + rx * wx.y;
        acc.z = Gv.z + bv.z + ry * wy.z + rx * wx.z;
        acc.w = Gv.w + bv.w + ry * wy.w + rx * wx.w;

        if (valid) {
            size_t cbase = ((size_t)(b * CELLS) + iyc * 64 + ixc) * 1024 + jc;
            float4 Av = *(const float4*)(g_A  + cbase);
            float4 Bv = *(const float4*)(g_Bt + cbase);
            acc.x += Av.x - Bv.x;
            acc.y += Av.y - Bv.y;
            acc.z += Av.z - Bv.z;
            acc.w += Av.w - Bv.w;
        }
        acc.x = fmaxf(acc.x, 0.f);
        acc.y = fmaxf(acc.y, 0.f);
        acc.z = fmaxf(acc.z, 0.f);
        acc.w = fmaxf(acc.w, 0.f);
        *(float4*)(g_h1 + ((size_t)pl * 4 + k) * 1024 + jc) = acc;
    }
}

// ---------------------------------------------------------------------------
// Final layer (128->2) + softmax blend for one chunk. One warp per pixel.
// ---------------------------------------------------------------------------
__global__ __launch_bounds__(256)
void k_final(const float* __restrict__ w5, const float* __restrict__ b5,
             float* __restrict__ out, int p0) {
    const int pl   = (int)((blockIdx.x * blockDim.x + threadIdx.x) >> 5);
    const int lane = threadIdx.x & 31;
    if (pl >= CH) return;

    const int c = lane << 2;                       // 4 channels per lane
    // w5 is [128,2] row-major: interleaved (col0,col1) per channel
    float4 wa = *(const float4*)(w5 + c * 2);      // ch c, c+1
    float4 wb = *(const float4*)(w5 + c * 2 + 4);  // ch c+2, c+3
    const float b50 = b5[0], b51 = b5[1];

    float p0v[4], p1v[4];
#pragma unroll
    for (int k = 0; k < 4; k++) {
        float4 v = *(const float4*)(g_h4 + ((size_t)pl * 4 + k) * 128 + c);
        float d0 = v.x * wa.x + v.y * wa.z + v.z * wb.x + v.w * wb.z;
        float d1 = v.x * wa.y + v.y * wa.w + v.z * wb.y + v.w * wb.w;
#pragma unroll
        for (int o = 16; o; o >>= 1) {
            d0 += __shfl_xor_sync(0xffffffffu, d0, o);
            d1 += __shfl_xor_sync(0xffffffffu, d1, o);
        }
        p0v[k] = d0 + b50;
        p1v[k] = d1 + b51;
    }
    float m = fmaxf(fmaxf(p1v[0], p1v[1]), fmaxf(p1v[2], p1v[3]));
    float e0 = expf(p1v[0] - m), e1 = expf(p1v[1] - m);
    float e2 = expf(p1v[2] - m), e3 = expf(p1v[3] - m);
    float s = e0 + e1 + e2 + e3;
    float r = (p0v[0] * e0 + p0v[1] * e1 + p0v[2] * e2 + p0v[3] * e3) / s;
    if (lane == 0) out[p0 + pl] = r;
}

// ---------------------------------------------------------------------------
// Launch
// ---------------------------------------------------------------------------
extern "C" void kernel_launch(void* const* d_in, const int* in_sizes, int n_in,
                              void* d_out, int out_size) {
    (void)in_sizes; (void)n_in; (void)out_size;
    const float* feat  = (const float*)d_in[0];
    const float* coord = (const float*)d_in[1];
    const float* hr    = (const float*)d_in[2];
    const float* lr    = (const float*)d_in[3];
    const float* w1    = (const float*)d_in[4];
    const float* b1    = (const float*)d_in[5];
    const float* w2    = (const float*)d_in[6];
    const float* b2    = (const float*)d_in[7];
    const float* w3    = (const float*)d_in[8];
    const float* b3    = (const float*)d_in[9];
    const float* w4    = (const float*)d_in[10];
    const float* b4    = (const float*)d_in[11];
    const float* w5    = (const float*)d_in[12];
    const float* b5    = (const float*)d_in[13];
    float* out = (float*)d_out;

    float *pXf, *pXlr, *pXhr, *pW1g, *pA, *pBt, *pG, *ph1, *ph2, *ph3, *ph4;
    cudaGetSymbolAddress((void**)&pXf,  g_Xf);
    cudaGetSymbolAddress((void**)&pXlr, g_Xlr);
    cudaGetSymbolAddress((void**)&pXhr, g_Xhr);
    cudaGetSymbolAddress((void**)&pW1g, g_W1g);
    cudaGetSymbolAddress((void**)&pA,   g_A);
    cudaGetSymbolAddress((void**)&pBt,  g_Bt);
    cudaGetSymbolAddress((void**)&pG,   g_G);
    cudaGetSymbolAddress((void**)&ph1,  g_h1);
    cudaGetSymbolAddress((void**)&ph2,  g_h2);
    cudaGetSymbolAddress((void**)&ph3,  g_h3);
    cudaGetSymbolAddress((void**)&ph4,  g_h4);

    dim3 tb(32, 8);
    // Pack channel-major tensors to row-major feature matrices
    k_transpose<<<dim3(CELLS / 32, CF / 32, 2), tb>>>(feat, pXf,  CF, CELLS);
    k_transpose<<<dim3(CELLS / 32, CF / 32, 2), tb>>>(lr,   pXlr, CF, CELLS);
    k_transpose<<<dim3(NPIX  / 32, CF / 32, 2), tb>>>(hr,   pXhr, CF, NPIX);
    k_w1g<<<512, 256>>>(w1);

    // Layer-1 factorized partial products over low-res cells (shared by all chunks)
    k_sgemm<false><<<dim3(8, 64), 256>>>(pXf,  w1,                      nullptr, pA,  2 * CELLS, 1024, 128);
    k_sgemm<false><<<dim3(8, 64), 256>>>(pXlr, w1 + (size_t)256 * 1024, nullptr, pBt, 2 * CELLS, 1024, 128);

    for (int ck = 0; ck < NCHUNK; ck++) {
        const int p0 = ck * CH;
        // hr-pixel partial product for this chunk's pixels
        k_sgemm<false><<<dim3(8, CH / 128), 256>>>(
            pXhr + (size_t)p0 * CF, pW1g, nullptr, pG, CH, 1024, 128);

        // Gather + rank-2 term + bias + ReLU -> h1 (chunk-local)
        k_assemble<<<CH, 256>>>(coord, w1, b1, p0);

        // Layers 2-4 (bias + ReLU fused)
        k_sgemm<true><<<dim3(4, RCH / 128), 256>>>(ph1, w2, b2, ph2, RCH, 512, 1024);
        k_sgemm<true><<<dim3(2, RCH / 128), 256>>>(ph2, w3, b3, ph3, RCH, 256, 512);
        k_sgemm<true><<<dim3(1, RCH / 128), 256>>>(ph3, w4, b4, ph4, RCH, 128, 256);

        // Layer 5 + softmax blend
        k_final<<<CH / 8, 256>>>(w5, b5, out, p0);
    }
}

// round 5
// speedup vs baseline: 5.7851x; 5.7851x over previous
#include <cuda_runtime.h>
#include <cuda_fp16.h>
#include <math.h>
#include <stdint.h>

// ---------------------------------------------------------------------------
// Problem constants
// ---------------------------------------------------------------------------
#define CF      128
#define CELLS   4096
#define NPIX    65536
#define PTOT    131072
#define CH      65536
#define NCHUNK  (PTOT / CH)
#define RCH     (CH * 4)      // 262144 MLP rows per chunk

// Wt offsets (elements) in packed transposed fp16 weight buffer
#define WT_W1G  0             // [1024,128]
#define WT_W2   131072        // [512,1024]
#define WT_W3   655360        // [256,512]
#define WT_W4   786432        // [128,256]
#define WT_TOT  819200

// ---------------------------------------------------------------------------
// Static device scratch (~1.39 GB)
// ---------------------------------------------------------------------------
__device__ __align__(16) float  g_Xf  [2 * CELLS * CF];            //   4 MB
__device__ __align__(16) float  g_Xlr [2 * CELLS * CF];            //   4 MB
__device__ __align__(16) __half g_Xhr [(size_t)PTOT * CF];         //  32 MB
__device__ __align__(16) float  g_A   [(size_t)2 * CELLS * 1024];  //  32 MB
__device__ __align__(16) float  g_Bt  [(size_t)2 * CELLS * 1024];  //  32 MB
__device__ __align__(16) float  g_G   [(size_t)CH * 1024];         // 256 MB
__device__ __align__(16) __half g_Wt  [WT_TOT];                    // 1.6 MB
__device__ __align__(16) __half g_h1  [(size_t)RCH * 1024];        // 512 MB
__device__ __align__(16) __half g_h2  [(size_t)RCH * 512];         // 256 MB
__device__ __align__(16) __half g_h3  [(size_t)RCH * 256];         // 128 MB
__device__ __align__(16) float  g_h4  [(size_t)RCH * 128];         // 128 MB

// ---------------------------------------------------------------------------
// Portable PTX helpers (all baseline sm_80+, valid for compute_103)
// ---------------------------------------------------------------------------
__device__ __forceinline__ uint32_t smem_u32(const void* p) {
    uint32_t a;
    asm("{ .reg .u64 t; cvta.to.shared.u64 t, %1; cvt.u32.u64 %0, t; }"
        : "=r"(a) : "l"(p));
    return a;
}
__device__ __forceinline__ void cp_async16(uint32_t dst, const void* src) {
    asm volatile("cp.async.cg.shared.global [%0], [%1], 16;" :: "r"(dst), "l"(src));
}
#define CP_COMMIT() asm volatile("cp.async.commit_group;" ::: "memory")
#define CP_WAIT(n)  asm volatile("cp.async.wait_group %0;" :: "n"(n) : "memory")

__device__ __forceinline__ void ldmatrix_x4(uint32_t& r0, uint32_t& r1,
                                            uint32_t& r2, uint32_t& r3, uint32_t a) {
    asm volatile("ldmatrix.sync.aligned.m8n8.x4.shared.b16 {%0,%1,%2,%3}, [%4];"
                 : "=r"(r0), "=r"(r1), "=r"(r2), "=r"(r3) : "r"(a));
}
__device__ __forceinline__ void ldmatrix_x2(uint32_t& r0, uint32_t& r1, uint32_t a) {
    asm volatile("ldmatrix.sync.aligned.m8n8.x2.shared.b16 {%0,%1}, [%2];"
                 : "=r"(r0), "=r"(r1) : "r"(a));
}
__device__ __forceinline__ void mma16816(float& c0, float& c1, float& c2, float& c3,
                                         uint32_t a0, uint32_t a1, uint32_t a2, uint32_t a3,
                                         uint32_t b0, uint32_t b1) {
    asm volatile("mma.sync.aligned.m16n8k16.row.col.f32.f16.f16.f32 "
                 "{%0,%1,%2,%3}, {%4,%5,%6,%7}, {%8,%9}, {%0,%1,%2,%3};"
                 : "+f"(c0), "+f"(c1), "+f"(c2), "+f"(c3)
                 : "r"(a0), "r"(a1), "r"(a2), "r"(a3), "r"(b0), "r"(b1));
}

// smem tile: 128 rows x 32 fp16 (64B/row), 4x 16B chunks/row, XOR swizzle so
// ldmatrix (8 rows/phase) and cp.async stores are conflict-free.
__device__ __forceinline__ uint32_t sw_off(int r, int g) {
    return (uint32_t)(r * 64 + ((g ^ ((r >> 1) & 3)) << 4));
}

// ---------------------------------------------------------------------------
// fp16 tensor-core GEMM: out[M,N] = act(A[M,K] @ Wt[N,K]^T + bias)
// CTA 128x128, K-step 32, 2-stage cp.async pipeline, 8 warps (2M x 4N).
// ---------------------------------------------------------------------------
template<bool RELU, bool OUTF32>
__global__ __launch_bounds__(256)
void k_hgemm(const __half* __restrict__ A, const __half* __restrict__ B,
             const float* __restrict__ bias,
             __half* __restrict__ outH, float* __restrict__ outF,
             int M, int N, int K) {
    __shared__ __align__(16) uint8_t sm[2][16384];   // per stage: A 8KB | B 8KB
    const uint32_t sb = smem_u32(sm);
    const int tid  = threadIdx.x;
    const int wid  = tid >> 5, lane = tid & 31;
    const int m0   = blockIdx.y * 128;
    const int n0   = blockIdx.x * 128;
    const int wm   = (wid & 1) * 64;
    const int wn   = (wid >> 1) * 32;

    float acc[4][4][4];
#pragma unroll
    for (int i = 0; i < 4; i++)
#pragma unroll
        for (int j = 0; j < 4; j++)
#pragma unroll
            for (int v = 0; v < 4; v++) acc[i][j][v] = 0.f;

    // loader: 1024 x 16B chunks (A 512 + B 512), 4 per thread
    auto load_tile = [&](int kt, int st) {
        const int k0 = kt * 32;
#pragma unroll
        for (int i = 0; i < 4; i++) {
            int c  = tid + i * 256;
            int cc = c & 511;
            int r  = cc >> 2, g = cc & 3;
            const __half* src = (c < 512)
                ? (A + (size_t)(m0 + r) * K + k0 + g * 8)
                : (B + (size_t)(n0 + r) * K + k0 + g * 8);
            uint32_t dst = sb + (uint32_t)st * 16384u + ((c < 512) ? 0u : 8192u)
                         + sw_off(r, g);
            cp_async16(dst, src);
        }
    };

    const int T = K >> 5;
    load_tile(0, 0);
    CP_COMMIT();

    for (int t = 0; t < T; t++) {
        const int st = t & 1;
        if (t + 1 < T) {
            load_tile(t + 1, st ^ 1);
            CP_COMMIT();
            CP_WAIT(1);
        } else {
            CP_WAIT(0);
        }
        __syncthreads();

        const uint32_t ab = sb + (uint32_t)st * 16384u;
        const uint32_t bb = ab + 8192u;
#pragma unroll
        for (int ks = 0; ks < 2; ks++) {
            uint32_t a[4][4], b[4][2];
#pragma unroll
            for (int mf = 0; mf < 4; mf++) {
                int mat = lane >> 3;
                int r = wm + mf * 16 + ((mat & 1) << 3) + (lane & 7);
                int g = ks * 2 + (mat >> 1);
                ldmatrix_x4(a[mf][0], a[mf][1], a[mf][2], a[mf][3], ab + sw_off(r, g));
            }
#pragma unroll
            for (int nf = 0; nf < 4; nf++) {
                int mat = (lane >> 3) & 1;
                int r = wn + nf * 8 + (lane & 7);
                int g = ks * 2 + mat;
                ldmatrix_x2(b[nf][0], b[nf][1], bb + sw_off(r, g));
            }
#pragma unroll
            for (int mf = 0; mf < 4; mf++)
#pragma unroll
                for (int nf = 0; nf < 4; nf++)
                    mma16816(acc[mf][nf][0], acc[mf][nf][1], acc[mf][nf][2], acc[mf][nf][3],
                             a[mf][0], a[mf][1], a[mf][2], a[mf][3],
                             b[nf][0], b[nf][1]);
        }
        __syncthreads();
    }

    // epilogue
#pragma unroll
    for (int nf = 0; nf < 4; nf++) {
        const int cb = n0 + wn + nf * 8 + 2 * (lane & 3);
        const float bz0 = bias ? bias[cb]     : 0.f;
        const float bz1 = bias ? bias[cb + 1] : 0.f;
#pragma unroll
        for (int mf = 0; mf < 4; mf++) {
            const int r0 = m0 + wm + mf * 16 + (lane >> 2);
            const int r1 = r0 + 8;
            float v0 = acc[mf][nf][0] + bz0, v1 = acc[mf][nf][1] + bz1;
            float v2 = acc[mf][nf][2] + bz0, v3 = acc[mf][nf][3] + bz1;
            if (RELU) {
                v0 = fmaxf(v0, 0.f); v1 = fmaxf(v1, 0.f);
                v2 = fmaxf(v2, 0.f); v3 = fmaxf(v3, 0.f);
            }
            if (OUTF32) {
                *(float2*)(outF + (size_t)r0 * N + cb) = make_float2(v0, v1);
                *(float2*)(outF + (size_t)r1 * N + cb) = make_float2(v2, v3);
            } else {
                *(__half2*)(outH + (size_t)r0 * N + cb) = __floats2half2_rn(v0, v1);
                *(__half2*)(outH + (size_t)r1 * N + cb) = __floats2half2_rn(v2, v3);
            }
        }
    }
}

// ---------------------------------------------------------------------------
// Transposes: fp32 (feat/lr) and fp16 (hr)
// ---------------------------------------------------------------------------
__global__ void k_transpose(const float* __restrict__ in, float* __restrict__ out,
                            int C, int S) {
    __shared__ float tile[32][33];
    const int b = blockIdx.z, s0 = blockIdx.x * 32, c0 = blockIdx.y * 32;
    const int tx = threadIdx.x, ty = threadIdx.y;
#pragma unroll
    for (int i = 0; i < 32; i += 8)
        tile[ty + i][tx] = in[(size_t)(b * C + c0 + ty + i) * S + (s0 + tx)];
    __syncthreads();
#pragma unroll
    for (int i = 0; i < 32; i += 8)
        out[(size_t)(b * S + s0 + ty + i) * C + (c0 + tx)] = tile[tx][ty + i];
}

__global__ void k_transpose_h(const float* __restrict__ in, __half* __restrict__ out,
                              int C, int S) {
    __shared__ float tile[32][33];
    const int b = blockIdx.z, s0 = blockIdx.x * 32, c0 = blockIdx.y * 32;
    const int tx = threadIdx.x, ty = threadIdx.y;
#pragma unroll
    for (int i = 0; i < 32; i += 8)
        tile[ty + i][tx] = in[(size_t)(b * C + c0 + ty + i) * S + (s0 + tx)];
    __syncthreads();
#pragma unroll
    for (int i = 0; i < 32; i += 8)
        out[(size_t)(b * S + s0 + ty + i) * C + (c0 + tx)] = __float2half(tile[tx][ty + i]);
}

// W1g^T: Wt[n*128+k] = fp16(w1[128+k][n] + w1[256+k][n])
__global__ void k_w1g_t(const float* __restrict__ w1) {
    int idx = blockIdx.x * 256 + threadIdx.x;   // < 131072
    int n = idx >> 7, k = idx & 127;
    g_Wt[WT_W1G + idx] =
        __float2half(w1[(size_t)(128 + k) * 1024 + n] + w1[(size_t)(256 + k) * 1024 + n]);
}

// W[K,N] -> Wt[N,K] fp16
__global__ void k_wsplit(const float* __restrict__ W, int K, int N, int wtoff) {
    int idx = blockIdx.x * 256 + threadIdx.x;
    if (idx >= N * K) return;
    int n = idx / K, k = idx % K;
    g_Wt[wtoff + idx] = __float2half(W[(size_t)k * N + n]);
}

// ---------------------------------------------------------------------------
// fp32 SGEMM for the small exact low-res tables (M=8192)
// ---------------------------------------------------------------------------
__global__ __launch_bounds__(256)
void k_sgemm(const float* __restrict__ A, const float* __restrict__ W,
             float* __restrict__ C, int M, int N, int K) {
    __shared__ float As[16][128];
    __shared__ float Ws[16][128];
    const int tid = threadIdx.x;
    const int m0 = blockIdx.y * 128, n0 = blockIdx.x * 128;
    const int ty = tid >> 4, tx = tid & 15;
    float acc[8][8];
#pragma unroll
    for (int i = 0; i < 8; i++)
#pragma unroll
        for (int j = 0; j < 8; j++) acc[i][j] = 0.f;
    for (int k0 = 0; k0 < K; k0 += 16) {
#pragma unroll
        for (int t = 0; t < 2; t++) {
            int idx = tid + t * 256;
            int ar = idx >> 2, ac = (idx & 3) << 2;
            float4 v = *(const float4*)(A + (size_t)(m0 + ar) * K + (k0 + ac));
            As[ac + 0][ar] = v.x; As[ac + 1][ar] = v.y;
            As[ac + 2][ar] = v.z; As[ac + 3][ar] = v.w;
            int wr = idx >> 5, wc = (idx & 31) << 2;
            *(float4*)&Ws[wr][wc] = *(const float4*)(W + (size_t)(k0 + wr) * N + (n0 + wc));
        }
        __syncthreads();
#pragma unroll
        for (int k = 0; k < 16; k++) {
            float a[8], w[8];
            *(float4*)&a[0] = *(const float4*)&As[k][ty * 8];
            *(float4*)&a[4] = *(const float4*)&As[k][ty * 8 + 4];
            *(float4*)&w[0] = *(const float4*)&Ws[k][tx * 8];
            *(float4*)&w[4] = *(const float4*)&Ws[k][tx * 8 + 4];
#pragma unroll
            for (int i = 0; i < 8; i++)
#pragma unroll
                for (int j = 0; j < 8; j++) acc[i][j] += a[i] * w[j];
        }
        __syncthreads();
    }
#pragma unroll
    for (int i = 0; i < 8; i++) {
        size_t row = (size_t)(m0 + ty * 8 + i);
        *(float4*)(C + row * N + n0 + tx * 8)     = *(float4*)&acc[i][0];
        *(float4*)(C + row * N + n0 + tx * 8 + 4) = *(float4*)&acc[i][4];
    }
}

// ---------------------------------------------------------------------------
// Layer-1 assembly -> h1 (fp16). Exact nearest_sample semantics in fp32.
// ---------------------------------------------------------------------------
__global__ __launch_bounds__(256)
void k_assemble(const float* __restrict__ coord,
                const float* __restrict__ w1,
                const float* __restrict__ b1, int p0) {
    const int pl = blockIdx.x;
    const int p  = p0 + pl;
    const int b  = p >> 16;
    const int jc = threadIdx.x << 2;

    const float y = coord[(size_t)p * 2 + 0];
    const float x = coord[(size_t)p * 2 + 1];

    float4 Gv = *(const float4*)(g_G + (size_t)pl * 1024 + jc);
    float4 wy = *(const float4*)(w1 + (size_t)384 * 1024 + jc);
    float4 wx = *(const float4*)(w1 + (size_t)385 * 1024 + jc);
    float4 bv = *(const float4*)(b1 + jc);

#pragma unroll
    for (int k = 0; k < 4; k++) {
        const float vx = (k >= 2) ? 1.f : -1.f;
        const float vy = (k & 1)  ? 1.f : -1.f;
        const float cy = y + vx * (1.f / 64.f);
        const float cx = x + vy * (1.f / 64.f);
        const float fy = (cy + 1.f) * 32.f - 0.5f;
        const float fx = (cx + 1.f) * 32.f - 0.5f;
        const int iy = (int)floorf(fy + 0.5f);
        const int ix = (int)floorf(fx + 0.5f);
        const bool valid = (iy >= 0) && (iy < 64) && (ix >= 0) && (ix < 64);
        const int iyc = min(max(iy, 0), 63);
        const int ixc = min(max(ix, 0), 63);
        const float qy = valid ? (-1.f + (1.f / 64.f) + (2.f / 64.f) * (float)iyc) : 0.f;
        const float qx = valid ? (-1.f + (1.f / 64.f) + (2.f / 64.f) * (float)ixc) : 0.f;
        const float ry = (y - qy) * 64.f;
        const float rx = (x - qx) * 64.f;

        float a0 = Gv.x + bv.x + ry * wy.x + rx * wx.x;
        float a1 = Gv.y + bv.y + ry * wy.y + rx * wx.y;
        float a2 = Gv.z + bv.z + ry * wy.z + rx * wx.z;
        float a3 = Gv.w + bv.w + ry * wy.w + rx * wx.w;
        if (valid) {
            size_t cbase = ((size_t)(b * CELLS) + iyc * 64 + ixc) * 1024 + jc;
            float4 Av = *(const float4*)(g_A  + cbase);
            float4 Bv = *(const float4*)(g_Bt + cbase);
            a0 += Av.x - Bv.x; a1 += Av.y - Bv.y;
            a2 += Av.z - Bv.z; a3 += Av.w - Bv.w;
        }
        __half h[4];
        h[0] = __float2half(fmaxf(a0, 0.f));
        h[1] = __float2half(fmaxf(a1, 0.f));
        h[2] = __float2half(fmaxf(a2, 0.f));
        h[3] = __float2half(fmaxf(a3, 0.f));
        *(uint2*)(g_h1 + ((size_t)pl * 4 + k) * 1024 + jc) = *(const uint2*)h;
    }
}

// ---------------------------------------------------------------------------
// Final layer (128->2) + softmax blend. One warp per pixel.
// ---------------------------------------------------------------------------
__global__ __launch_bounds__(256)
void k_final(const float* __restrict__ w5, const float* __restrict__ b5,
             float* __restrict__ out, int p0) {
    const int pl   = (int)((blockIdx.x * blockDim.x + threadIdx.x) >> 5);
    const int lane = threadIdx.x & 31;
    if (pl >= CH) return;
    const int c = lane << 2;
    float4 wa = *(const float4*)(w5 + c * 2);
    float4 wb = *(const float4*)(w5 + c * 2 + 4);
    const float b50 = b5[0], b51 = b5[1];
    float p0v[4], p1v[4];
#pragma unroll
    for (int k = 0; k < 4; k++) {
        float4 v = *(const float4*)(g_h4 + ((size_t)pl * 4 + k) * 128 + c);
        float d0 = v.x * wa.x + v.y * wa.z + v.z * wb.x + v.w * wb.z;
        float d1 = v.x * wa.y + v.y * wa.w + v.z * wb.y + v.w * wb.w;
#pragma unroll
        for (int o = 16; o; o >>= 1) {
            d0 += __shfl_xor_sync(0xffffffffu, d0, o);
            d1 += __shfl_xor_sync(0xffffffffu, d1, o);
        }
        p0v[k] = d0 + b50;
        p1v[k] = d1 + b51;
    }
    float m = fmaxf(fmaxf(p1v[0], p1v[1]), fmaxf(p1v[2], p1v[3]));
    float e0 = expf(p1v[0] - m), e1 = expf(p1v[1] - m);
    float e2 = expf(p1v[2] - m), e3 = expf(p1v[3] - m);
    float s = e0 + e1 + e2 + e3;
    float r = (p0v[0] * e0 + p0v[1] * e1 + p0v[2] * e2 + p0v[3] * e3) / s;
    if (lane == 0) out[p0 + pl] = r;
}

// ---------------------------------------------------------------------------
// Launch
// ---------------------------------------------------------------------------
extern "C" void kernel_launch(void* const* d_in, const int* in_sizes, int n_in,
                              void* d_out, int out_size) {
    (void)in_sizes; (void)n_in; (void)out_size;
    const float* feat  = (const float*)d_in[0];
    const float* coord = (const float*)d_in[1];
    const float* hr    = (const float*)d_in[2];
    const float* lr    = (const float*)d_in[3];
    const float* w1    = (const float*)d_in[4];
    const float* b1    = (const float*)d_in[5];
    const float* w2    = (const float*)d_in[6];
    const float* b2    = (const float*)d_in[7];
    const float* w3    = (const float*)d_in[8];
    const float* b3    = (const float*)d_in[9];
    const float* w4    = (const float*)d_in[10];
    const float* b4    = (const float*)d_in[11];
    const float* w5    = (const float*)d_in[12];
    const float* b5    = (const float*)d_in[13];
    float* out = (float*)d_out;

    float *pXf, *pXlr, *pA, *pBt, *pG, *ph4;
    __half *pXhr, *pWt, *ph1, *ph2, *ph3;
    cudaGetSymbolAddress((void**)&pXf,  g_Xf);
    cudaGetSymbolAddress((void**)&pXlr, g_Xlr);
    cudaGetSymbolAddress((void**)&pXhr, g_Xhr);
    cudaGetSymbolAddress((void**)&pA,   g_A);
    cudaGetSymbolAddress((void**)&pBt,  g_Bt);
    cudaGetSymbolAddress((void**)&pG,   g_G);
    cudaGetSymbolAddress((void**)&pWt,  g_Wt);
    cudaGetSymbolAddress((void**)&ph1,  g_h1);
    cudaGetSymbolAddress((void**)&ph2,  g_h2);
    cudaGetSymbolAddress((void**)&ph3,  g_h3);
    cudaGetSymbolAddress((void**)&ph4,  g_h4);

    dim3 tb(32, 8);
    k_transpose  <<<dim3(CELLS / 32, CF / 32, 2), tb>>>(feat, pXf,  CF, CELLS);
    k_transpose  <<<dim3(CELLS / 32, CF / 32, 2), tb>>>(lr,   pXlr, CF, CELLS);
    k_transpose_h<<<dim3(NPIX  / 32, CF / 32, 2), tb>>>(hr,   pXhr, CF, NPIX);

    k_w1g_t <<<512, 256>>>(w1);
    k_wsplit<<<(512 * 1024 + 255) / 256, 256>>>(w2, 1024, 512, WT_W2);
    k_wsplit<<<(256 * 512  + 255) / 256, 256>>>(w3, 512,  256, WT_W3);
    k_wsplit<<<(128 * 256  + 255) / 256, 256>>>(w4, 256,  128, WT_W4);

    // exact fp32 low-res tables
    k_sgemm<<<dim3(8, 64), 256>>>(pXf,  w1,                      pA,  2 * CELLS, 1024, 128);
    k_sgemm<<<dim3(8, 64), 256>>>(pXlr, w1 + (size_t)256 * 1024, pBt, 2 * CELLS, 1024, 128);

    for (int ck = 0; ck < NCHUNK; ck++) {
        const int p0 = ck * CH;

        // G = Xhr @ W1g^T   (fp32 out, no bias/relu)
        k_hgemm<false, true><<<dim3(8, CH / 128), 256>>>(
            pXhr + (size_t)p0 * CF, pWt + WT_W1G, nullptr,
            nullptr, pG, CH, 1024, 128);

        k_assemble<<<CH, 256>>>(coord, w1, b1, p0);

        k_hgemm<true, false><<<dim3(4, RCH / 128), 256>>>(
            ph1, pWt + WT_W2, b2, ph2, nullptr, RCH, 512, 1024);
        k_hgemm<true, false><<<dim3(2, RCH / 128), 256>>>(
            ph2, pWt + WT_W3, b3, ph3, nullptr, RCH, 256, 512);
        k_hgemm<true, true><<<dim3(1, RCH / 128), 256>>>(
            ph3, pWt + WT_W4, b4, nullptr, ph4, RCH, 128, 256);

        k_final<<<CH / 8, 256>>>(w5, b5, out, p0);
    }
}